// round 1
// baseline (speedup 1.0000x reference)
#include <cuda_runtime.h>
#include <math.h>

#define NN 8192
#define DD 64
#define BM 128
#define BN 128
#define BK 32
#define LDA 132          // padded leading dim for As: keeps 16B align, reduces STS conflicts
#define SPLITK 4

// ---------------- scratch (device globals: allocation-free) ----------------
__device__ float g_rowsum[NN];
__device__ float g_colsum[NN];
__device__ float g_rinv[NN];
__device__ float g_cinv[NN];
__device__ __align__(16) float g_P[NN * 128];   // rinv[a]*[itemW1 | user]  (for adj^T pass)
__device__ __align__(16) float g_Q[NN * 128];   // cinv[b]*[userW1 | item]  (for adj   pass)
__device__ __align__(16) float g_Ru[NN * 128];  // raw adj^T @ P
__device__ __align__(16) float g_Ri[NN * 128];  // raw adj   @ Q

__device__ __forceinline__ unsigned long long pack2(float lo, float hi) {
    unsigned long long r;
    asm("mov.b64 %0, {%1, %2};" : "=l"(r) : "f"(lo), "f"(hi));
    return r;
}

// ---------------- 1) zero scratch accumulators (graph-replay safe) ----------------
__global__ void zero_kernel() {
    int idx = blockIdx.x * blockDim.x + threadIdx.x;
    int stride = gridDim.x * blockDim.x;
    for (int i = idx; i < NN * 128; i += stride) { g_Ru[i] = 0.f; g_Ri[i] = 0.f; }
    if (idx < NN) { g_rowsum[idx] = 0.f; g_colsum[idx] = 0.f; }
}

// ---------------- 2) fused row+col sums of adjacency (one 256MB pass) ----------------
// grid (8, 32), 256 threads. Each thread owns 4 consecutive columns, iterates 256 rows
// (staggered per x-block to decorrelate same-address row atomics).
__global__ void sums_kernel(const float* __restrict__ adj) {
    int tid = threadIdx.x;
    int c4 = (blockIdx.x * 256 + tid) * 4;
    int r0 = blockIdx.y * 256;
    int off = (blockIdx.x * 32) & 255;
    float s0 = 0.f, s1 = 0.f, s2 = 0.f, s3 = 0.f;
#pragma unroll 4
    for (int i = 0; i < 256; i++) {
        int r = r0 + ((i + off) & 255);
        float4 v = *(const float4*)&adj[(size_t)r * NN + c4];
        s0 += v.x; s1 += v.y; s2 += v.z; s3 += v.w;
        float rs = (v.x + v.y) + (v.z + v.w);
        rs += __shfl_down_sync(0xffffffffu, rs, 16);
        rs += __shfl_down_sync(0xffffffffu, rs, 8);
        rs += __shfl_down_sync(0xffffffffu, rs, 4);
        rs += __shfl_down_sync(0xffffffffu, rs, 2);
        rs += __shfl_down_sync(0xffffffffu, rs, 1);
        if ((tid & 31) == 0) atomicAdd(&g_rowsum[r], rs);
    }
    atomicAdd(&g_colsum[c4 + 0], s0);
    atomicAdd(&g_colsum[c4 + 1], s1);
    atomicAdd(&g_colsum[c4 + 2], s2);
    atomicAdd(&g_colsum[c4 + 3], s3);
}

// ---------------- 3) rinv / cinv ----------------
__global__ void scale_kernel() {
    int i = blockIdx.x * 256 + threadIdx.x;
    if (i < NN) {
        g_rinv[i] = 1.0f / sqrtf(g_rowsum[i]);
        g_cinv[i] = 1.0f / sqrtf(g_colsum[i]);
    }
}

// ---------------- 4) build P and Q: scl * [src@W1 | pass] ----------------
// grid (512, 2), 256 threads; 16 rows per block; thread = (row = tid>>4, 4 cols = (tid&15)*4)
__global__ void prep_kernel(const float* __restrict__ user, const float* __restrict__ item,
                            const float* __restrict__ W1) {
    int var = blockIdx.y;  // 0 -> P (src=item, pass=user, scale=rinv), 1 -> Q
    const float* src = var ? user : item;
    const float* pas = var ? item : user;
    const float* scl = var ? g_cinv : g_rinv;
    float* out = var ? g_Q : g_P;

    __shared__ __align__(16) float Ws[DD * DD];
    __shared__ float Xs[16 * DD];
    int tid = threadIdx.x;
    for (int i = tid; i < DD * DD; i += 256) Ws[i] = W1[i];
    int r0 = blockIdx.x * 16;
    for (int i = tid; i < 16 * DD; i += 256) Xs[i] = src[r0 * DD + i];
    __syncthreads();

    int row = tid >> 4;
    int cg = (tid & 15) * 4;
    float a0 = 0.f, a1 = 0.f, a2 = 0.f, a3 = 0.f;
#pragma unroll 8
    for (int k = 0; k < DD; k++) {
        float x = Xs[row * DD + k];
        float4 w = *(const float4*)&Ws[k * DD + cg];
        a0 += x * w.x; a1 += x * w.y; a2 += x * w.z; a3 += x * w.w;
    }
    int gr = r0 + row;
    float s = scl[gr];
    float* o = out + gr * 128;
    o[cg + 0] = s * a0; o[cg + 1] = s * a1; o[cg + 2] = s * a2; o[cg + 3] = s * a3;
    const float* p = pas + gr * DD;
    o[64 + cg + 0] = s * p[cg + 0];
    o[64 + cg + 1] = s * p[cg + 1];
    o[64 + cg + 2] = s * p[cg + 2];
    o[64 + cg + 3] = s * p[cg + 3];
}

// ---------------- 5) big GEMM: C[8192,128] (+)= op(adj) @ B ----------------
template <int TRANS>
__device__ __forceinline__ void load_tile(const float* __restrict__ adj,
                                          const float* __restrict__ Bm,
                                          int m0, int kt, int tid,
                                          float4 (&ra)[4], float4 (&rb)[4]) {
#pragma unroll
    for (int t = 0; t < 4; t++) {
        int i = tid + 256 * t;
        int k = i >> 5, q = i & 31;
        if (TRANS) {
            ra[t] = *(const float4*)&adj[(size_t)(kt + k) * NN + m0 + q * 4];
        } else {
            int m = i >> 3, kq = i & 7;
            ra[t] = *(const float4*)&adj[(size_t)(m0 + m) * NN + kt + kq * 4];
        }
        rb[t] = *(const float4*)&Bm[(kt + k) * 128 + q * 4];
    }
}

template <int TRANS>
__global__ void __launch_bounds__(256, 2) gemm_kernel(const float* __restrict__ adj) {
    const float* __restrict__ Bm = TRANS ? g_P : g_Q;
    float* Cp = TRANS ? g_Ru : g_Ri;

    __shared__ __align__(16) float As[BK][LDA];
    __shared__ __align__(16) float Bs[BK][BN];

    int tid = threadIdx.x;
    int m0 = blockIdx.x * BM;
    int kbase = blockIdx.y * (NN / SPLITK);
    int mg = (tid & 15) * 8;   // 8 m per thread (packed in pairs)
    int ng = (tid >> 4) * 8;   // 8 n per thread

    unsigned long long acc[4][8];
#pragma unroll
    for (int a = 0; a < 4; a++)
#pragma unroll
        for (int b = 0; b < 8; b++) acc[a][b] = 0ull;

    const int NITER = (NN / SPLITK) / BK;
    float4 ra[4], rb[4];
    load_tile<TRANS>(adj, Bm, m0, kbase, tid, ra, rb);

    for (int it = 0; it < NITER; it++) {
        __syncthreads();
        // stage registers -> smem
#pragma unroll
        for (int t = 0; t < 4; t++) {
            int i = tid + 256 * t;
            int k = i >> 5, q = i & 31;
            if (TRANS) {
                *(float4*)&As[k][q * 4] = ra[t];
            } else {
                int m = i >> 3, kq = i & 7;
                As[kq * 4 + 0][m] = ra[t].x;
                As[kq * 4 + 1][m] = ra[t].y;
                As[kq * 4 + 2][m] = ra[t].z;
                As[kq * 4 + 3][m] = ra[t].w;
            }
            *(float4*)&Bs[k][q * 4] = rb[t];
        }
        __syncthreads();
        if (it + 1 < NITER)
            load_tile<TRANS>(adj, Bm, m0, kbase + (it + 1) * BK, tid, ra, rb);

#pragma unroll 4
        for (int k = 0; k < BK; k++) {
            float4 a0 = *(const float4*)&As[k][mg];
            float4 a1 = *(const float4*)&As[k][mg + 4];
            float4 b0 = *(const float4*)&Bs[k][ng];
            float4 b1 = *(const float4*)&Bs[k][ng + 4];
            unsigned long long am[4];
            am[0] = pack2(a0.x, a0.y); am[1] = pack2(a0.z, a0.w);
            am[2] = pack2(a1.x, a1.y); am[3] = pack2(a1.z, a1.w);
            float bv[8] = {b0.x, b0.y, b0.z, b0.w, b1.x, b1.y, b1.z, b1.w};
#pragma unroll
            for (int n = 0; n < 8; n++) {
                unsigned long long bb = pack2(bv[n], bv[n]);
#pragma unroll
                for (int mp = 0; mp < 4; mp++)
                    asm("fma.rn.f32x2 %0, %1, %2, %0;"
                        : "+l"(acc[mp][n]) : "l"(am[mp]), "l"(bb));
            }
        }
    }

    // split-K reduction via atomics
#pragma unroll
    for (int mp = 0; mp < 4; mp++)
#pragma unroll
        for (int n = 0; n < 8; n++) {
            unsigned lo, hi;
            asm("mov.b64 {%0, %1}, %2;" : "=r"(lo), "=r"(hi) : "l"(acc[mp][n]));
            int m = m0 + mg + mp * 2;
            atomicAdd(&Cp[m * 128 + ng + n], __uint_as_float(lo));
            atomicAdd(&Cp[(m + 1) * 128 + ng + n], __uint_as_float(hi));
        }
}

// ---------------- 6) epilogue: scale, elementwise W2 term, residual, leaky_relu ----------------
// grid (512, 2), 256 threads; 16 rows per block
__global__ void final_kernel(const float* __restrict__ user, const float* __restrict__ item,
                             const float* __restrict__ W2, float* __restrict__ out) {
    int var = blockIdx.y;  // 0 -> updated_user (uses Ru, cinv, src=item, tgt=user)
    const float* R = var ? g_Ri : g_Ru;
    const float* scl = var ? g_rinv : g_cinv;
    const float* src = var ? user : item;
    const float* tgt = var ? item : user;
    float* o = out + (size_t)var * NN * DD;

    __shared__ __align__(16) float Ws[DD * DD];
    __shared__ float Hs[16 * DD];
    int tid = threadIdx.x;
    for (int i = tid; i < DD * DD; i += 256) Ws[i] = W2[i];

    int r0 = blockIdx.x * 16;
    int row = tid >> 4;
    int cg = (tid & 15) * 4;
    int gr = r0 + row;
    float s = scl[gr];
#pragma unroll
    for (int j = 0; j < 4; j++)
        Hs[row * DD + cg + j] = src[gr * DD + cg + j] * (s * R[gr * 128 + 64 + cg + j]);
    __syncthreads();

    float acc[4] = {0.f, 0.f, 0.f, 0.f};
#pragma unroll 8
    for (int k = 0; k < DD; k++) {
        float h = Hs[row * DD + k];
        float4 w = *(const float4*)&Ws[k * DD + cg];
        acc[0] += h * w.x; acc[1] += h * w.y; acc[2] += h * w.z; acc[3] += h * w.w;
    }
#pragma unroll
    for (int j = 0; j < 4; j++) {
        float x = s * R[gr * 128 + cg + j] + acc[j] + tgt[gr * DD + cg + j];
        o[gr * DD + cg + j] = x > 0.f ? x : 0.2f * x;
    }
}

// ---------------- launch ----------------
extern "C" void kernel_launch(void* const* d_in, const int* in_sizes, int n_in,
                              void* d_out, int out_size) {
    const float* user = (const float*)d_in[0];
    const float* item = (const float*)d_in[1];
    const float* adj  = (const float*)d_in[2];
    const float* W1   = (const float*)d_in[3];
    const float* W2   = (const float*)d_in[4];
    float* out = (float*)d_out;

    zero_kernel<<<2048, 256>>>();
    sums_kernel<<<dim3(8, 32), 256>>>(adj);
    scale_kernel<<<32, 256>>>();
    prep_kernel<<<dim3(512, 2), 256>>>(user, item, W1);
    gemm_kernel<0><<<dim3(64, SPLITK), 256>>>(adj);  // Ri = adj   @ Q
    gemm_kernel<1><<<dim3(64, SPLITK), 256>>>(adj);  // Ru = adj^T @ P
    final_kernel<<<dim3(512, 2), 256>>>(user, item, W2, out);
}

// round 3
// speedup vs baseline: 2.1042x; 2.1042x over previous
#include <cuda_runtime.h>
#include <cuda_bf16.h>
#include <math.h>
#include <stdint.h>

#define NN 8192
#define DD 64

// ---------------- device scratch (allocation-free) ----------------
__device__ float g_rowsum[NN];
__device__ float g_colsum[NN];
__device__ float g_rinv[NN];
__device__ float g_cinv[NN];
__device__ __align__(16) __nv_bfloat16 g_Qt[128 * NN];  // Q^T: [n][k] bf16, k contiguous
__device__ __align__(16) __nv_bfloat16 g_Pt[128 * NN];  // P^T
__device__ __align__(16) float g_Ru[NN * 128];          // adj^T @ P
__device__ __align__(16) float g_Ri[NN * 128];          // adj   @ Q

__device__ __forceinline__ uint32_t smem_u32(const void* p) {
    uint32_t a;
    asm("{ .reg .u64 t; cvta.to.shared.u64 t, %1; cvt.u32.u64 %0, t; }" : "=r"(a) : "l"(p));
    return a;
}
__device__ __forceinline__ uint32_t bf2pk(float lo, float hi) {
    __nv_bfloat162 b = __float22bfloat162_rn(make_float2(lo, hi));
    return *(uint32_t*)&b;
}

// ---------------- 1) zero sums ----------------
__global__ void zero_kernel() {
    int i = blockIdx.x * 256 + threadIdx.x;
    if (i < NN) { g_rowsum[i] = 0.f; g_colsum[i] = 0.f; }
}

// ---------------- 2) fused row+col sums (one 256MB pass) ----------------
__global__ void sums_kernel(const float* __restrict__ adj) {
    int tid = threadIdx.x;
    int c4 = (blockIdx.x * 256 + tid) * 4;
    int r0 = blockIdx.y * 256;
    int off = (blockIdx.x * 32) & 255;
    float s0 = 0.f, s1 = 0.f, s2 = 0.f, s3 = 0.f;
#pragma unroll 4
    for (int i = 0; i < 256; i++) {
        int r = r0 + ((i + off) & 255);
        float4 v = *(const float4*)&adj[(size_t)r * NN + c4];
        s0 += v.x; s1 += v.y; s2 += v.z; s3 += v.w;
        float rs = (v.x + v.y) + (v.z + v.w);
        rs += __shfl_down_sync(0xffffffffu, rs, 16);
        rs += __shfl_down_sync(0xffffffffu, rs, 8);
        rs += __shfl_down_sync(0xffffffffu, rs, 4);
        rs += __shfl_down_sync(0xffffffffu, rs, 2);
        rs += __shfl_down_sync(0xffffffffu, rs, 1);
        if ((tid & 31) == 0) atomicAdd(&g_rowsum[r], rs);
    }
    atomicAdd(&g_colsum[c4 + 0], s0);
    atomicAdd(&g_colsum[c4 + 1], s1);
    atomicAdd(&g_colsum[c4 + 2], s2);
    atomicAdd(&g_colsum[c4 + 3], s3);
}

// ---------------- 3) rinv / cinv ----------------
__global__ void scale_kernel() {
    int i = blockIdx.x * 256 + threadIdx.x;
    if (i < NN) {
        g_rinv[i] = 1.0f / sqrtf(g_rowsum[i]);
        g_cinv[i] = 1.0f / sqrtf(g_colsum[i]);
    }
}

// ---------------- 4) build Qt/Pt (bf16, [n][k]) ----------------
// grid (512, 2), 256 threads; 16 k-rows per block
__global__ void __launch_bounds__(256) prep_kernel(const float* __restrict__ user,
                                                   const float* __restrict__ item,
                                                   const float* __restrict__ W1) {
    int var = blockIdx.y;  // 0 -> Pt (src=item, scale=rinv), 1 -> Qt (src=user, scale=cinv)
    const float* src = var ? user : item;
    const float* pas = var ? item : user;
    const float* scl = var ? g_cinv : g_rinv;
    __nv_bfloat16* out = var ? g_Qt : g_Pt;

    __shared__ __align__(16) float Ws[DD * DD];
    __shared__ float Xs[16 * DD];
    __shared__ __nv_bfloat16 T[128 * 18];  // [n][k-local]
    int tid = threadIdx.x;
    for (int i = tid; i < DD * DD; i += 256) Ws[i] = W1[i];
    int k0 = blockIdx.x * 16;
    for (int i = tid; i < 16 * DD; i += 256) Xs[i] = src[k0 * DD + i];
    __syncthreads();

    int row = tid >> 4;       // local k
    int g4 = (tid & 15) * 4;  // n group
    float a0 = 0.f, a1 = 0.f, a2 = 0.f, a3 = 0.f;
#pragma unroll 8
    for (int k = 0; k < DD; k++) {
        float x = Xs[row * DD + k];
        float4 w = *(const float4*)&Ws[k * DD + g4];
        a0 += x * w.x; a1 += x * w.y; a2 += x * w.z; a3 += x * w.w;
    }
    int gr = k0 + row;
    float s = scl[gr];
    T[(g4 + 0) * 18 + row] = __float2bfloat16(s * a0);
    T[(g4 + 1) * 18 + row] = __float2bfloat16(s * a1);
    T[(g4 + 2) * 18 + row] = __float2bfloat16(s * a2);
    T[(g4 + 3) * 18 + row] = __float2bfloat16(s * a3);
    const float* p = pas + gr * DD;
#pragma unroll
    for (int j = 0; j < 4; j++)
        T[(64 + g4 + j) * 18 + row] = __float2bfloat16(s * p[g4 + j]);
    __syncthreads();

    if (tid < 128) {
        int n = tid;
        __align__(16) __nv_bfloat16 v[16];
#pragma unroll
        for (int k = 0; k < 16; k++) v[k] = T[n * 18 + k];
        uint4* dst = (uint4*)(out + (size_t)n * NN + k0);
        dst[0] = ((uint4*)v)[0];
        dst[1] = ((uint4*)v)[1];
    }
}

// ---------------- 5) tensor-core GEMM via mma.sync (bf16), fp32 A converted on the fly ----
// C[8192,128] = op(adj) @ B.  grid (64, 2): y=0 -> Ri = adj @ Q, y=1 -> Ru = adj^T @ P
#define BK 64
#define LDA0 72    // As [128][72] bf16 (TRANS=0)
#define LDA1 136   // As [64][136] bf16 (TRANS=1)
#define LDB 72     // Bs [128][72]

__global__ void __launch_bounds__(256, 1) gemm_kernel(const float* __restrict__ adj) {
    __shared__ __align__(16) __nv_bfloat16 sA[9216];      // 18432 B
    __shared__ __align__(16) __nv_bfloat16 sB[128 * LDB]; // 18432 B

    int tid = threadIdx.x;
    int lane = tid & 31, wid = tid >> 5;
    int warpM = wid & 3, warpN = wid >> 2;  // 4 x 2 warp grid: warp tile 32m x 64n
    int TRANS = blockIdx.y;
    int m0 = blockIdx.x * 128;
    const __nv_bfloat16* Bg = TRANS ? g_Pt : g_Qt;
    float* Cg = TRANS ? g_Ru : g_Ri;

    // gmem load assignments (per thread: 8 float4 of A, 4 uint4 of B)
    int arow = TRANS ? (tid >> 2) : (tid >> 1);          // k-row : m-row
    int acol = TRANS ? ((tid & 3) * 32) : ((tid & 1) * 32);
    const float* gA = TRANS ? (adj + (size_t)arow * NN + m0 + acol)
                            : (adj + (size_t)(m0 + arow) * NN + acol);
    size_t gA_kstep = TRANS ? (size_t)BK * NN : (size_t)BK;  // advance per iter (floats)
    int brow = tid >> 1, bh = tid & 1;
    const __nv_bfloat16* gB = Bg + (size_t)brow * NN + bh * 32;

    // smem store addresses (bf16 element offsets)
    int sAoff = TRANS ? (arow * LDA1 + acol) : (arow * LDA0 + acol);
    int sBoff = brow * LDB + bh * 32;

    // ldmatrix source addresses (bytes, via smem u32)
    uint32_t sAb = smem_u32(sA), sBb = smem_u32(sB);
    uint32_t aaddr[2], baddr[4];
#pragma unroll
    for (int f = 0; f < 2; f++) {
        int e;
        if (TRANS)
            e = (((lane >> 4) & 1) * 8 + (lane & 7)) * LDA1 + warpM * 32 + f * 16 + ((lane >> 3) & 1) * 8;
        else
            e = (warpM * 32 + f * 16 + (lane & 15)) * LDA0 + (lane >> 4) * 8;
        aaddr[f] = sAb + e * 2;
    }
#pragma unroll
    for (int g = 0; g < 4; g++) {
        int e = (warpN * 64 + g * 16 + ((lane >> 4) << 3) + (lane & 7)) * LDB + ((lane >> 3) & 1) * 8;
        baddr[g] = sBb + e * 2;
    }
    uint32_t a_kstep = TRANS ? (16 * LDA1 * 2) : (16 * 2);  // byte advance per k-step of 16
    uint32_t b_kstep = 16 * 2;

    float c[2][8][4];
#pragma unroll
    for (int f = 0; f < 2; f++)
#pragma unroll
        for (int n = 0; n < 8; n++)
#pragma unroll
            for (int j = 0; j < 4; j++) c[f][n][j] = 0.f;

    const int NITER = NN / BK;
    float4 ra[8];
    uint4 rb[4];
#pragma unroll
    for (int j = 0; j < 8; j++) ra[j] = *(const float4*)(gA + j * 4);
#pragma unroll
    for (int j = 0; j < 4; j++) rb[j] = *(const uint4*)(gB + j * 8);

    for (int it = 0; it < NITER; it++) {
        __syncthreads();
        // convert + stage to smem
#pragma unroll
        for (int j = 0; j < 4; j++) {
            uint4 pk;
            pk.x = bf2pk(ra[2 * j].x, ra[2 * j].y);
            pk.y = bf2pk(ra[2 * j].z, ra[2 * j].w);
            pk.z = bf2pk(ra[2 * j + 1].x, ra[2 * j + 1].y);
            pk.w = bf2pk(ra[2 * j + 1].z, ra[2 * j + 1].w);
            *(uint4*)&sA[sAoff + j * 8] = pk;
            *(uint4*)&sB[sBoff + j * 8] = rb[j];
        }
        __syncthreads();
        if (it + 1 < NITER) {
            const float* nA = gA + (size_t)(it + 1) * gA_kstep;
            const __nv_bfloat16* nB = gB + (size_t)(it + 1) * BK;
#pragma unroll
            for (int j = 0; j < 8; j++) ra[j] = *(const float4*)(nA + j * 4);
#pragma unroll
            for (int j = 0; j < 4; j++) rb[j] = *(const uint4*)(nB + j * 8);
        }

#pragma unroll
        for (int ks = 0; ks < 4; ks++) {
            uint32_t am[2][4], bn[4][4];
#pragma unroll
            for (int f = 0; f < 2; f++) {
                uint32_t addr = aaddr[f] + ks * a_kstep;
                if (TRANS)
                    asm volatile("ldmatrix.sync.aligned.m8n8.x4.trans.shared.b16 {%0,%1,%2,%3}, [%4];"
                                 : "=r"(am[f][0]), "=r"(am[f][1]), "=r"(am[f][2]), "=r"(am[f][3])
                                 : "r"(addr));
                else
                    asm volatile("ldmatrix.sync.aligned.m8n8.x4.shared.b16 {%0,%1,%2,%3}, [%4];"
                                 : "=r"(am[f][0]), "=r"(am[f][1]), "=r"(am[f][2]), "=r"(am[f][3])
                                 : "r"(addr));
            }
#pragma unroll
            for (int g = 0; g < 4; g++) {
                uint32_t addr = baddr[g] + ks * b_kstep;
                asm volatile("ldmatrix.sync.aligned.m8n8.x4.shared.b16 {%0,%1,%2,%3}, [%4];"
                             : "=r"(bn[g][0]), "=r"(bn[g][1]), "=r"(bn[g][2]), "=r"(bn[g][3])
                             : "r"(addr));
            }
#pragma unroll
            for (int f = 0; f < 2; f++)
#pragma unroll
                for (int g = 0; g < 4; g++)
#pragma unroll
                    for (int s = 0; s < 2; s++) {
                        int n = g * 2 + s;
                        asm volatile(
                            "mma.sync.aligned.m16n8k16.row.col.f32.bf16.bf16.f32 "
                            "{%0,%1,%2,%3}, {%4,%5,%6,%7}, {%8,%9}, {%0,%1,%2,%3};"
                            : "+f"(c[f][n][0]), "+f"(c[f][n][1]), "+f"(c[f][n][2]), "+f"(c[f][n][3])
                            : "r"(am[f][0]), "r"(am[f][1]), "r"(am[f][2]), "r"(am[f][3]),
                              "r"(bn[g][s * 2]), "r"(bn[g][s * 2 + 1]));
                    }
        }
    }

    // store C
#pragma unroll
    for (int f = 0; f < 2; f++) {
        int row = m0 + warpM * 32 + f * 16 + (lane >> 2);
#pragma unroll
        for (int n = 0; n < 8; n++) {
            int col = warpN * 64 + n * 8 + (lane & 3) * 2;
            *(float2*)&Cg[(size_t)row * 128 + col] = make_float2(c[f][n][0], c[f][n][1]);
            *(float2*)&Cg[(size_t)(row + 8) * 128 + col] = make_float2(c[f][n][2], c[f][n][3]);
        }
    }
}

// ---------------- 6) epilogue ----------------
__global__ void __launch_bounds__(256) final_kernel(const float* __restrict__ user,
                                                    const float* __restrict__ item,
                                                    const float* __restrict__ W2,
                                                    float* __restrict__ out) {
    int var = blockIdx.y;  // 0 -> updated_user (Ru, cinv), 1 -> updated_item (Ri, rinv)
    const float* R = var ? g_Ri : g_Ru;
    const float* scl = var ? g_rinv : g_cinv;
    const float* src = var ? user : item;
    const float* tgt = var ? item : user;
    float* o = out + (size_t)var * NN * DD;

    __shared__ __align__(16) float Ws[DD * DD];
    __shared__ float Hs[16 * DD];
    int tid = threadIdx.x;
    for (int i = tid; i < DD * DD; i += 256) Ws[i] = W2[i];

    int r0 = blockIdx.x * 16;
    int row = tid >> 4;
    int cg = (tid & 15) * 4;
    int gr = r0 + row;
    float s = scl[gr];
#pragma unroll
    for (int j = 0; j < 4; j++)
        Hs[row * DD + cg + j] = src[gr * DD + cg + j] * (s * R[gr * 128 + 64 + cg + j]);
    __syncthreads();

    float acc[4] = {0.f, 0.f, 0.f, 0.f};
#pragma unroll 8
    for (int k = 0; k < DD; k++) {
        float hh = Hs[row * DD + k];
        float4 w = *(const float4*)&Ws[k * DD + cg];
        acc[0] += hh * w.x; acc[1] += hh * w.y; acc[2] += hh * w.z; acc[3] += hh * w.w;
    }
#pragma unroll
    for (int j = 0; j < 4; j++) {
        float x = s * R[gr * 128 + cg + j] + acc[j] + tgt[gr * DD + cg + j];
        o[gr * DD + cg + j] = x > 0.f ? x : 0.2f * x;
    }
}

// ---------------- launch ----------------
extern "C" void kernel_launch(void* const* d_in, const int* in_sizes, int n_in,
                              void* d_out, int out_size) {
    const float* user = (const float*)d_in[0];
    const float* item = (const float*)d_in[1];
    const float* adj  = (const float*)d_in[2];
    const float* W1   = (const float*)d_in[3];
    const float* W2   = (const float*)d_in[4];
    float* out = (float*)d_out;

    zero_kernel<<<32, 256>>>();
    sums_kernel<<<dim3(8, 32), 256>>>(adj);
    scale_kernel<<<32, 256>>>();
    prep_kernel<<<dim3(512, 2), 256>>>(user, item, W1);
    gemm_kernel<<<dim3(64, 2), 256>>>(adj);
    final_kernel<<<dim3(512, 2), 256>>>(user, item, W2, out);
}

// round 4
// speedup vs baseline: 2.3378x; 1.1110x over previous
#include <cuda_runtime.h>
#include <cuda_bf16.h>
#include <math.h>
#include <stdint.h>

#define NN 8192
#define DD 64

// ---------------- device scratch (allocation-free) ----------------
__device__ float g_rowsum[NN];
__device__ float g_colsum[NN];
__device__ float g_rinv[NN];
__device__ float g_cinv[NN];
__device__ __align__(16) __nv_bfloat16 g_adjbf[67108864];   // adj   bf16 row-major
__device__ __align__(16) __nv_bfloat16 g_adjtbf[67108864];  // adj^T bf16 row-major
__device__ __align__(16) __nv_bfloat16 g_Qt[128 * NN];      // Q^T [n][k]
__device__ __align__(16) __nv_bfloat16 g_Pt[128 * NN];      // P^T [n][k]
__device__ __align__(16) float g_Ru[NN * 128];              // adj^T @ P
__device__ __align__(16) float g_Ri[NN * 128];              // adj   @ Q

__device__ __forceinline__ uint32_t smem_u32(const void* p) {
    uint32_t a;
    asm("{ .reg .u64 t; cvta.to.shared.u64 t, %1; cvt.u32.u64 %0, t; }" : "=r"(a) : "l"(p));
    return a;
}
__device__ __forceinline__ void cpa16(uint32_t s, const void* g) {
    asm volatile("cp.async.cg.shared.global [%0], [%1], 16;" :: "r"(s), "l"(g) : "memory");
}

// ---------------- 1) zero sums ----------------
__global__ void zero_kernel() {
    int i = blockIdx.x * 256 + threadIdx.x;
    if (i < NN) { g_rowsum[i] = 0.f; g_colsum[i] = 0.f; }
}

// ---------------- 2) fused convert (fp32 -> bf16 + bf16^T) + row/col sums ----------------
// grid (64, 64), 256 threads; 128x128 tile per block
__global__ void __launch_bounds__(256) convert_kernel(const float* __restrict__ adj) {
    __shared__ __nv_bfloat16 S[128 * 130];
    int tid = threadIdx.x;
    int r0 = blockIdx.y * 128, c0 = blockIdx.x * 128;
    int r = tid >> 1, h = tid & 1;

    const float4* g = (const float4*)(adj + (size_t)(r0 + r) * NN + c0 + h * 64);
    __nv_bfloat16* ob = g_adjbf + (size_t)(r0 + r) * NN + c0 + h * 64;
    float rs = 0.f;
#pragma unroll
    for (int j = 0; j < 16; j += 2) {
        float4 v0 = g[j], v1 = g[j + 1];
        rs += ((v0.x + v0.y) + (v0.z + v0.w)) + ((v1.x + v1.y) + (v1.z + v1.w));
        __nv_bfloat162 b0 = __float22bfloat162_rn(make_float2(v0.x, v0.y));
        __nv_bfloat162 b1 = __float22bfloat162_rn(make_float2(v0.z, v0.w));
        __nv_bfloat162 b2 = __float22bfloat162_rn(make_float2(v1.x, v1.y));
        __nv_bfloat162 b3 = __float22bfloat162_rn(make_float2(v1.z, v1.w));
        uint4 pk;
        pk.x = *(uint32_t*)&b0; pk.y = *(uint32_t*)&b1;
        pk.z = *(uint32_t*)&b2; pk.w = *(uint32_t*)&b3;
        *(uint4*)&ob[j * 4] = pk;
        *(__nv_bfloat162*)&S[r * 130 + h * 64 + j * 4 + 0] = b0;
        *(__nv_bfloat162*)&S[r * 130 + h * 64 + j * 4 + 2] = b1;
        *(__nv_bfloat162*)&S[r * 130 + h * 64 + j * 4 + 4] = b2;
        *(__nv_bfloat162*)&S[r * 130 + h * 64 + j * 4 + 6] = b3;
    }
    rs += __shfl_xor_sync(0xffffffffu, rs, 1);
    if (h == 0) atomicAdd(&g_rowsum[r0 + r], rs);
    __syncthreads();

    int c = tid >> 1;
    float cs = 0.f;
    __nv_bfloat16* ot = g_adjtbf + (size_t)(c0 + c) * NN + r0 + h * 64;
#pragma unroll
    for (int j = 0; j < 8; j++) {
        __align__(16) __nv_bfloat16 v[8];
#pragma unroll
        for (int i = 0; i < 8; i++) {
            v[i] = S[(h * 64 + j * 8 + i) * 130 + c];
            cs += __bfloat162float(v[i]);
        }
        *(uint4*)&ot[j * 8] = *(uint4*)v;
    }
    cs += __shfl_xor_sync(0xffffffffu, cs, 1);
    if (h == 0) atomicAdd(&g_colsum[c0 + c], cs);
}

// ---------------- 3) rinv / cinv ----------------
__global__ void scale_kernel() {
    int i = blockIdx.x * 256 + threadIdx.x;
    if (i < NN) {
        g_rinv[i] = 1.0f / sqrtf(g_rowsum[i]);
        g_cinv[i] = 1.0f / sqrtf(g_colsum[i]);
    }
}

// ---------------- 4) build Qt/Pt (bf16, [n][k]) ----------------
__global__ void __launch_bounds__(256) prep_kernel(const float* __restrict__ user,
                                                   const float* __restrict__ item,
                                                   const float* __restrict__ W1) {
    int var = blockIdx.y;  // 0 -> Pt (src=item, scale=rinv), 1 -> Qt (src=user, scale=cinv)
    const float* src = var ? user : item;
    const float* pas = var ? item : user;
    const float* scl = var ? g_cinv : g_rinv;
    __nv_bfloat16* out = var ? g_Qt : g_Pt;

    __shared__ __align__(16) float Ws[DD * DD];
    __shared__ float Xs[16 * DD];
    __shared__ __nv_bfloat16 T[128 * 18];
    int tid = threadIdx.x;
    for (int i = tid; i < DD * DD; i += 256) Ws[i] = W1[i];
    int k0 = blockIdx.x * 16;
    for (int i = tid; i < 16 * DD; i += 256) Xs[i] = src[k0 * DD + i];
    __syncthreads();

    int row = tid >> 4;
    int g4 = (tid & 15) * 4;
    float a0 = 0.f, a1 = 0.f, a2 = 0.f, a3 = 0.f;
#pragma unroll 8
    for (int k = 0; k < DD; k++) {
        float x = Xs[row * DD + k];
        float4 w = *(const float4*)&Ws[k * DD + g4];
        a0 += x * w.x; a1 += x * w.y; a2 += x * w.z; a3 += x * w.w;
    }
    int gr = k0 + row;
    float s = scl[gr];
    T[(g4 + 0) * 18 + row] = __float2bfloat16(s * a0);
    T[(g4 + 1) * 18 + row] = __float2bfloat16(s * a1);
    T[(g4 + 2) * 18 + row] = __float2bfloat16(s * a2);
    T[(g4 + 3) * 18 + row] = __float2bfloat16(s * a3);
    const float* p = pas + gr * DD;
#pragma unroll
    for (int j = 0; j < 4; j++)
        T[(64 + g4 + j) * 18 + row] = __float2bfloat16(s * p[g4 + j]);
    __syncthreads();

    if (tid < 128) {
        int n = tid;
        __align__(16) __nv_bfloat16 v[16];
#pragma unroll
        for (int k = 0; k < 16; k++) v[k] = T[n * 18 + k];
        uint4* dst = (uint4*)(out + (size_t)n * NN + k0);
        dst[0] = ((uint4*)v)[0];
        dst[1] = ((uint4*)v)[1];
    }
}

// ---------------- 5) cp.async 4-stage bf16 mma.sync GEMM ----------------
// C[8192,128] = A_bf16 @ B.  grid (64, 2): y=0 -> Ri = adjbf @ Qt, y=1 -> Ru = adjtbf @ Pt
// smem per stage: A 128x64 bf16 (16KB) + B 128x64 bf16 (16KB); 4 stages = 128KB dynamic.
// Layout: row r = 8 chunks of 16B; chunk c stored at (c ^ (r & 7)) -> conflict-free ldmatrix.
#define NST 4
#define ASTG 16384
#define NITER 128

__global__ void __launch_bounds__(256, 1) gemm_kernel() {
    extern __shared__ char sm[];
    uint32_t sA = smem_u32(sm);
    uint32_t sB = sA + NST * ASTG;

    int tid = threadIdx.x;
    int lane = tid & 31, wid = tid >> 5;
    int warpM = wid & 3, warpN = wid >> 2;  // 4x2 warps, warp tile 32m x 64n
    int m0 = blockIdx.x * 128;
    const __nv_bfloat16* Ag = blockIdx.y ? g_adjtbf : g_adjbf;
    const __nv_bfloat16* Bg = blockIdx.y ? g_Pt : g_Qt;
    float* Cg = blockIdx.y ? g_Ru : g_Ri;

    // cp.async assignments: thread t -> row t>>1, chunks (t&1)*4 .. +3
    int lr = tid >> 1, lc0 = (tid & 1) * 4;
    const char* gAp = (const char*)(Ag + (size_t)(m0 + lr) * NN) + lc0 * 16;
    const char* gBp = (const char*)(Bg + (size_t)lr * NN) + lc0 * 16;
    uint32_t sto[4];
#pragma unroll
    for (int j = 0; j < 4; j++)
        sto[j] = lr * 128 + (((lc0 + j) ^ (lr & 7)) << 4);

    // ldmatrix per-thread constants
    int aRow[2], aX[2];
#pragma unroll
    for (int f = 0; f < 2; f++) {
        aRow[f] = warpM * 32 + f * 16 + (lane & 15);
        aX[f] = aRow[f] & 7;
    }
    int ah = lane >> 4;
    int bRow[4], bX[4];
#pragma unroll
    for (int g = 0; g < 4; g++) {
        bRow[g] = warpN * 64 + g * 16 + (lane >> 4) * 8 + (lane & 7);
        bX[g] = bRow[g] & 7;
    }
    int bh = (lane >> 3) & 1;

    float c[2][8][4];
#pragma unroll
    for (int f = 0; f < 2; f++)
#pragma unroll
        for (int n = 0; n < 8; n++)
#pragma unroll
            for (int j = 0; j < 4; j++) c[f][n][j] = 0.f;

    // prologue: stages 0..2
#pragma unroll
    for (int s = 0; s < NST - 1; s++) {
        uint32_t da = sA + s * ASTG, db = sB + s * ASTG;
        size_t kb = (size_t)s * 128;  // 64 bf16 = 128 bytes per stage step
#pragma unroll
        for (int j = 0; j < 4; j++) {
            cpa16(da + sto[j], gAp + kb + j * 16);
            cpa16(db + sto[j], gBp + kb + j * 16);
        }
        asm volatile("cp.async.commit_group;" ::: "memory");
    }

    for (int it = 0; it < NITER; it++) {
        if (it <= NITER - 3)      asm volatile("cp.async.wait_group 2;" ::: "memory");
        else if (it == NITER - 2) asm volatile("cp.async.wait_group 1;" ::: "memory");
        else                      asm volatile("cp.async.wait_group 0;" ::: "memory");
        __syncthreads();

        if (it + NST - 1 < NITER) {
            int s = (it + NST - 1) & (NST - 1);
            uint32_t da = sA + s * ASTG, db = sB + s * ASTG;
            size_t kb = (size_t)(it + NST - 1) * 128;
#pragma unroll
            for (int j = 0; j < 4; j++) {
                cpa16(da + sto[j], gAp + kb + j * 16);
                cpa16(db + sto[j], gBp + kb + j * 16);
            }
            asm volatile("cp.async.commit_group;" ::: "memory");
        }

        uint32_t ba = sA + (it & (NST - 1)) * ASTG;
        uint32_t bb = sB + (it & (NST - 1)) * ASTG;
#pragma unroll
        for (int ks = 0; ks < 4; ks++) {
            uint32_t am[2][4], bn[4][4];
#pragma unroll
            for (int f = 0; f < 2; f++) {
                uint32_t addr = ba + aRow[f] * 128 + ((((ks << 1) | ah) ^ aX[f]) << 4);
                asm volatile("ldmatrix.sync.aligned.m8n8.x4.shared.b16 {%0,%1,%2,%3}, [%4];"
                             : "=r"(am[f][0]), "=r"(am[f][1]), "=r"(am[f][2]), "=r"(am[f][3])
                             : "r"(addr));
            }
#pragma unroll
            for (int g = 0; g < 4; g++) {
                uint32_t addr = bb + bRow[g] * 128 + ((((ks << 1) | bh) ^ bX[g]) << 4);
                asm volatile("ldmatrix.sync.aligned.m8n8.x4.shared.b16 {%0,%1,%2,%3}, [%4];"
                             : "=r"(bn[g][0]), "=r"(bn[g][1]), "=r"(bn[g][2]), "=r"(bn[g][3])
                             : "r"(addr));
            }
#pragma unroll
            for (int f = 0; f < 2; f++)
#pragma unroll
                for (int g = 0; g < 4; g++)
#pragma unroll
                    for (int s = 0; s < 2; s++) {
                        int n = g * 2 + s;
                        asm volatile(
                            "mma.sync.aligned.m16n8k16.row.col.f32.bf16.bf16.f32 "
                            "{%0,%1,%2,%3}, {%4,%5,%6,%7}, {%8,%9}, {%0,%1,%2,%3};"
                            : "+f"(c[f][n][0]), "+f"(c[f][n][1]), "+f"(c[f][n][2]), "+f"(c[f][n][3])
                            : "r"(am[f][0]), "r"(am[f][1]), "r"(am[f][2]), "r"(am[f][3]),
                              "r"(bn[g][s * 2]), "r"(bn[g][s * 2 + 1]));
                    }
        }
    }

    // store C
#pragma unroll
    for (int f = 0; f < 2; f++) {
        int row = m0 + warpM * 32 + f * 16 + (lane >> 2);
#pragma unroll
        for (int n = 0; n < 8; n++) {
            int col = warpN * 64 + n * 8 + (lane & 3) * 2;
            *(float2*)&Cg[(size_t)row * 128 + col] = make_float2(c[f][n][0], c[f][n][1]);
            *(float2*)&Cg[(size_t)(row + 8) * 128 + col] = make_float2(c[f][n][2], c[f][n][3]);
        }
    }
}

// ---------------- 6) epilogue ----------------
__global__ void __launch_bounds__(256) final_kernel(const float* __restrict__ user,
                                                    const float* __restrict__ item,
                                                    const float* __restrict__ W2,
                                                    float* __restrict__ out) {
    int var = blockIdx.y;  // 0 -> updated_user (Ru, cinv), 1 -> updated_item (Ri, rinv)
    const float* R = var ? g_Ri : g_Ru;
    const float* scl = var ? g_rinv : g_cinv;
    const float* src = var ? user : item;
    const float* tgt = var ? item : user;
    float* o = out + (size_t)var * NN * DD;

    __shared__ __align__(16) float Ws[DD * DD];
    __shared__ float Hs[16 * DD];
    int tid = threadIdx.x;
    for (int i = tid; i < DD * DD; i += 256) Ws[i] = W2[i];

    int r0 = blockIdx.x * 16;
    int row = tid >> 4;
    int cg = (tid & 15) * 4;
    int gr = r0 + row;
    float s = scl[gr];
#pragma unroll
    for (int j = 0; j < 4; j++)
        Hs[row * DD + cg + j] = src[gr * DD + cg + j] * (s * R[gr * 128 + 64 + cg + j]);
    __syncthreads();

    float acc[4] = {0.f, 0.f, 0.f, 0.f};
#pragma unroll 8
    for (int k = 0; k < DD; k++) {
        float hh = Hs[row * DD + k];
        float4 w = *(const float4*)&Ws[k * DD + cg];
        acc[0] += hh * w.x; acc[1] += hh * w.y; acc[2] += hh * w.z; acc[3] += hh * w.w;
    }
#pragma unroll
    for (int j = 0; j < 4; j++) {
        float x = s * R[gr * 128 + cg + j] + acc[j] + tgt[gr * DD + cg + j];
        o[gr * DD + cg + j] = x > 0.f ? x : 0.2f * x;
    }
}

// ---------------- launch ----------------
extern "C" void kernel_launch(void* const* d_in, const int* in_sizes, int n_in,
                              void* d_out, int out_size) {
    const float* user = (const float*)d_in[0];
    const float* item = (const float*)d_in[1];
    const float* adj  = (const float*)d_in[2];
    const float* W1   = (const float*)d_in[3];
    const float* W2   = (const float*)d_in[4];
    float* out = (float*)d_out;

    cudaFuncSetAttribute(gemm_kernel, cudaFuncAttributeMaxDynamicSharedMemorySize,
                         2 * NST * ASTG);

    zero_kernel<<<32, 256>>>();
    convert_kernel<<<dim3(64, 64), 256>>>(adj);
    scale_kernel<<<32, 256>>>();
    prep_kernel<<<dim3(512, 2), 256>>>(user, item, W1);
    gemm_kernel<<<dim3(64, 2), 256, 2 * NST * ASTG>>>();
    final_kernel<<<dim3(512, 2), 256>>>(user, item, W2, out);
}

// round 5
// speedup vs baseline: 3.1642x; 1.3535x over previous
#include <cuda_runtime.h>
#include <cuda_bf16.h>
#include <math.h>
#include <stdint.h>

#define NN 8192
#define DD 64
#define ONES 0x3F803F80u

// ---------------- device scratch (allocation-free) ----------------
__device__ float g_rowsum[NN];
__device__ float g_colsum[NN];
__device__ float g_rinv[NN];
__device__ float g_cinv[NN];
__device__ __align__(16) __nv_bfloat16 g_adjbf[67108864];  // adj bf16 row-major
__device__ __align__(16) __nv_bfloat16 g_Qt[128 * NN];     // Q^T [n][k]
__device__ __align__(16) __nv_bfloat16 g_Pt[128 * NN];     // P^T [n][k]
__device__ __align__(16) float g_Ru[NN * 128];             // adj^T @ P  ([a][128])
__device__ __align__(16) float g_Ri[NN * 128];             // adj   @ Q  ([a][128])

__device__ __forceinline__ uint32_t smem_u32(const void* p) {
    uint32_t a;
    asm("{ .reg .u64 t; cvta.to.shared.u64 t, %1; cvt.u32.u64 %0, t; }" : "=r"(a) : "l"(p));
    return a;
}
__device__ __forceinline__ void cpa16(uint32_t s, const void* g) {
    asm volatile("cp.async.cg.shared.global [%0], [%1], 16;" :: "r"(s), "l"(g) : "memory");
}
__device__ __forceinline__ uint32_t bf2pk(float lo, float hi) {
    __nv_bfloat162 b = __float22bfloat162_rn(make_float2(lo, hi));
    return *(uint32_t*)&b;
}
__device__ __forceinline__ void mma_bf16(float* c, uint32_t a0, uint32_t a1, uint32_t a2,
                                         uint32_t a3, uint32_t b0, uint32_t b1) {
    asm volatile(
        "mma.sync.aligned.m16n8k16.row.col.f32.bf16.bf16.f32 "
        "{%0,%1,%2,%3}, {%4,%5,%6,%7}, {%8,%9}, {%0,%1,%2,%3};"
        : "+f"(c[0]), "+f"(c[1]), "+f"(c[2]), "+f"(c[3])
        : "r"(a0), "r"(a1), "r"(a2), "r"(a3), "r"(b0), "r"(b1));
}

// ---------------- 1) zero colsum (graph-replay safe) ----------------
__global__ void zero_kernel() {
    int i = blockIdx.x * 256 + threadIdx.x;
    if (i < NN) g_colsum[i] = 0.f;
}

// ---------------- 2) pure streaming convert fp32 -> bf16 ----------------
__global__ void __launch_bounds__(256) convert_kernel(const float* __restrict__ adj) {
    int gid = blockIdx.x * 256 + threadIdx.x;
    const int NF4 = NN * NN / 4;
    const int STR = gridDim.x * 256;
    for (int i = gid; i < NF4; i += STR) {
        float4 v = ((const float4*)adj)[i];
        uint2 o;
        o.x = bf2pk(v.x, v.y);
        o.y = bf2pk(v.z, v.w);
        ((uint2*)g_adjbf)[i] = o;
    }
}

// ---------------- 3) tensor-core row/col sums of adjbf ----------------
// grid 128: CTA owns 64-row slab [64][8192]; iterates 64 tiles of [64][128].
// rowsum: warps 0-3 accumulate tile@ones locally (exclusive rows, direct store).
// colsum: all 8 warps: ones@tile via ldmatrix.trans, flushed per-iter via atomics.
#define SROWS 64
#define SCOLS 128
__global__ void __launch_bounds__(256) sums_kernel() {
    __shared__ __align__(16) __nv_bfloat16 st[3][SROWS * SCOLS];
    int tid = threadIdx.x, lane = tid & 31, wid = tid >> 5;
    int r0 = blockIdx.x * SROWS;

    int lr = tid >> 2, lc0 = (tid & 3) * 4;
    const char* gp = (const char*)(g_adjbf + (size_t)(r0 + lr) * NN) + lc0 * 16;
    uint32_t sbase = smem_u32(st);
    uint32_t sto[4];
#pragma unroll
    for (int j = 0; j < 4; j++)
        sto[j] = lr * 256 + (((lc0 + j) ^ (lr & 7)) << 4);

    // prologue: 2 stages
#pragma unroll
    for (int s = 0; s < 2; s++) {
#pragma unroll
        for (int j = 0; j < 4; j++)
            cpa16(sbase + s * (SROWS * SCOLS * 2) + sto[j], gp + (size_t)s * 256 + j * 16);
        asm volatile("cp.async.commit_group;" ::: "memory");
    }

    float rc[4] = {0.f, 0.f, 0.f, 0.f};  // rowsum accum (warps 0-3)

    for (int it = 0; it < 64; it++) {
        if (it < 62)       asm volatile("cp.async.wait_group 1;" ::: "memory");
        else               asm volatile("cp.async.wait_group 0;" ::: "memory");
        __syncthreads();
        if (it + 2 < 64) {
            int s = (it + 2) % 3;
#pragma unroll
            for (int j = 0; j < 4; j++)
                cpa16(sbase + s * (SROWS * SCOLS * 2) + sto[j],
                      gp + (size_t)(it + 2) * 256 + j * 16);
            asm volatile("cp.async.commit_group;" ::: "memory");
        }
        uint32_t buf = sbase + (it % 3) * (SROWS * SCOLS * 2);

        // --- rowsum: warps 0-3, m-chunk = wid (rows wid*16..+15), k = 128 cols ---
        if (wid < 4) {
            int aRow = wid * 16 + (lane & 15);
            int ax = aRow & 7;
#pragma unroll
            for (int kc = 0; kc < 8; kc++) {
                uint32_t a0, a1, a2, a3;
                uint32_t addr = buf + aRow * 256 + ((((kc << 1) | (lane >> 4)) ^ ax) << 4);
                asm volatile("ldmatrix.sync.aligned.m8n8.x4.shared.b16 {%0,%1,%2,%3}, [%4];"
                             : "=r"(a0), "=r"(a1), "=r"(a2), "=r"(a3) : "r"(addr));
                mma_bf16(rc, a0, a1, a2, a3, ONES, ONES);
            }
        }

        // --- colsum: all warps, n16 = wid*16, k = 64 rows ---
        float cc[2][4] = {{0.f, 0.f, 0.f, 0.f}, {0.f, 0.f, 0.f, 0.f}};
        int srow0 = ((lane >> 4) & 1) * 8 + (lane & 7);
        int sc = wid * 2 + ((lane >> 3) & 1);
#pragma unroll
        for (int kc = 0; kc < 4; kc++) {
            int srow = kc * 16 + srow0;
            uint32_t b0, b1, b2, b3;
            uint32_t addr = buf + srow * 256 + ((sc ^ (srow & 7)) << 4);
            asm volatile("ldmatrix.sync.aligned.m8n8.x4.trans.shared.b16 {%0,%1,%2,%3}, [%4];"
                         : "=r"(b0), "=r"(b1), "=r"(b2), "=r"(b3) : "r"(addr));
            mma_bf16(cc[0], ONES, ONES, ONES, ONES, b0, b2);
            mma_bf16(cc[1], ONES, ONES, ONES, ONES, b1, b3);
        }
        if (lane < 4) {
            int colb = it * 128 + wid * 16 + 2 * lane;
            atomicAdd(&g_colsum[colb + 0], cc[0][0]);
            atomicAdd(&g_colsum[colb + 1], cc[0][1]);
            atomicAdd(&g_colsum[colb + 8], cc[1][0]);
            atomicAdd(&g_colsum[colb + 9], cc[1][1]);
        }
    }

    if (wid < 4 && (lane & 3) == 0) {
        int row = r0 + wid * 16 + (lane >> 2);
        g_rowsum[row] = rc[0];
        g_rowsum[row + 8] = rc[2];
    }
}

// ---------------- 4) rinv / cinv ----------------
__global__ void scale_kernel() {
    int i = blockIdx.x * 256 + threadIdx.x;
    if (i < NN) {
        g_rinv[i] = 1.0f / sqrtf(g_rowsum[i]);
        g_cinv[i] = 1.0f / sqrtf(g_colsum[i]);
    }
}

// ---------------- 5) build Qt/Pt (bf16, [n][k]); 64 k-rows per block ----------------
__global__ void __launch_bounds__(256) prep_kernel(const float* __restrict__ user,
                                                   const float* __restrict__ item,
                                                   const float* __restrict__ W1) {
    int var = blockIdx.y;  // 0 -> Pt (src=item, scale=rinv), 1 -> Qt (src=user, scale=cinv)
    const float* src = var ? user : item;
    const float* pas = var ? item : user;
    const float* scl = var ? g_cinv : g_rinv;
    __nv_bfloat16* out = var ? g_Qt : g_Pt;

    __shared__ __align__(16) float Ws[DD * DD];
    __shared__ __align__(16) float Xs[64 * DD];
    __shared__ __nv_bfloat16 T[128 * 66];
    int tid = threadIdx.x;
    int k0 = blockIdx.x * 64;
    for (int i = tid; i < DD * DD; i += 256) Ws[i] = W1[i];
    for (int i = tid; i < 64 * DD; i += 256) Xs[i] = src[k0 * DD + i];
    __syncthreads();

    int g4 = (tid & 15) * 4;
#pragma unroll
    for (int r4 = 0; r4 < 4; r4++) {
        int row = r4 * 16 + (tid >> 4);
        float a0 = 0.f, a1 = 0.f, a2 = 0.f, a3 = 0.f;
#pragma unroll 8
        for (int k = 0; k < DD; k++) {
            float x = Xs[row * DD + k];
            float4 w = *(const float4*)&Ws[k * DD + g4];
            a0 += x * w.x; a1 += x * w.y; a2 += x * w.z; a3 += x * w.w;
        }
        int gr = k0 + row;
        float s = scl[gr];
        T[(g4 + 0) * 66 + row] = __float2bfloat16(s * a0);
        T[(g4 + 1) * 66 + row] = __float2bfloat16(s * a1);
        T[(g4 + 2) * 66 + row] = __float2bfloat16(s * a2);
        T[(g4 + 3) * 66 + row] = __float2bfloat16(s * a3);
        const float* p = pas + gr * DD;
#pragma unroll
        for (int j = 0; j < 4; j++)
            T[(64 + g4 + j) * 66 + row] = __float2bfloat16(s * p[g4 + j]);
    }
    __syncthreads();

    if (tid < 128) {
        int n = tid;
#pragma unroll
        for (int cchunk = 0; cchunk < 8; cchunk++) {
            __align__(16) __nv_bfloat16 v[8];
#pragma unroll
            for (int k = 0; k < 8; k++) v[k] = T[n * 66 + cchunk * 8 + k];
            *(uint4*)(out + (size_t)n * NN + k0 + cchunk * 8) = *(uint4*)v;
        }
    }
}

// ---------------- 6) GEMMs (cp.async 4-stage, bf16 mma.sync) ----------------
// grid (64, 2):
//  y=0: Ri[m-tile][128] = adjbf[m-tile][:] @ Qt           (A rows, B k-contig)
//  y=1: RuT[128][n-tile] = Pt @ adjbf[:][n-tile]  -> smem transpose -> g_Ru[n][m]
#define NST 4
#define ASTG 16384
#define NITER 128

__global__ void __launch_bounds__(256, 1) gemm_kernel() {
    extern __shared__ char sm[];
    uint32_t sA = smem_u32(sm);
    uint32_t sB = sA + NST * ASTG;

    int tid = threadIdx.x;
    int lane = tid & 31, wid = tid >> 5;
    int warpM = wid & 3, warpN = wid >> 2;  // 4x2 warps, warp tile 32m x 64n

    float c[2][8][4];
#pragma unroll
    for (int f = 0; f < 2; f++)
#pragma unroll
        for (int n = 0; n < 8; n++)
#pragma unroll
            for (int j = 0; j < 4; j++) c[f][n][j] = 0.f;

    if (blockIdx.y == 0) {
        // ---------------- GEMM1 ----------------
        int m0 = blockIdx.x * 128;
        int lr = tid >> 1, lc0 = (tid & 1) * 4;
        const char* gAp = (const char*)(g_adjbf + (size_t)(m0 + lr) * NN) + lc0 * 16;
        const char* gBp = (const char*)(g_Qt + (size_t)lr * NN) + lc0 * 16;
        uint32_t sto[4];
#pragma unroll
        for (int j = 0; j < 4; j++)
            sto[j] = lr * 128 + (((lc0 + j) ^ (lr & 7)) << 4);

        int aRow[2], aX[2];
#pragma unroll
        for (int f = 0; f < 2; f++) {
            aRow[f] = warpM * 32 + f * 16 + (lane & 15);
            aX[f] = aRow[f] & 7;
        }
        int ah = lane >> 4;
        int bRow[4], bX[4];
#pragma unroll
        for (int g = 0; g < 4; g++) {
            bRow[g] = warpN * 64 + g * 16 + (lane >> 4) * 8 + (lane & 7);
            bX[g] = bRow[g] & 7;
        }
        int bh = (lane >> 3) & 1;

#pragma unroll
        for (int s = 0; s < NST - 1; s++) {
            uint32_t da = sA + s * ASTG, db = sB + s * ASTG;
#pragma unroll
            for (int j = 0; j < 4; j++) {
                cpa16(da + sto[j], gAp + (size_t)s * 128 + j * 16);
                cpa16(db + sto[j], gBp + (size_t)s * 128 + j * 16);
            }
            asm volatile("cp.async.commit_group;" ::: "memory");
        }

        for (int it = 0; it < NITER; it++) {
            if (it <= NITER - 3)      asm volatile("cp.async.wait_group 2;" ::: "memory");
            else if (it == NITER - 2) asm volatile("cp.async.wait_group 1;" ::: "memory");
            else                      asm volatile("cp.async.wait_group 0;" ::: "memory");
            __syncthreads();
            if (it + NST - 1 < NITER) {
                int s = (it + NST - 1) & (NST - 1);
                uint32_t da = sA + s * ASTG, db = sB + s * ASTG;
                size_t kb = (size_t)(it + NST - 1) * 128;
#pragma unroll
                for (int j = 0; j < 4; j++) {
                    cpa16(da + sto[j], gAp + kb + j * 16);
                    cpa16(db + sto[j], gBp + kb + j * 16);
                }
                asm volatile("cp.async.commit_group;" ::: "memory");
            }
            uint32_t ba = sA + (it & (NST - 1)) * ASTG;
            uint32_t bb = sB + (it & (NST - 1)) * ASTG;
#pragma unroll
            for (int ks = 0; ks < 4; ks++) {
                uint32_t am[2][4], bn[4][4];
#pragma unroll
                for (int f = 0; f < 2; f++) {
                    uint32_t addr = ba + aRow[f] * 128 + ((((ks << 1) | ah) ^ aX[f]) << 4);
                    asm volatile("ldmatrix.sync.aligned.m8n8.x4.shared.b16 {%0,%1,%2,%3}, [%4];"
                                 : "=r"(am[f][0]), "=r"(am[f][1]), "=r"(am[f][2]), "=r"(am[f][3])
                                 : "r"(addr));
                }
#pragma unroll
                for (int g = 0; g < 4; g++) {
                    uint32_t addr = bb + bRow[g] * 128 + ((((ks << 1) | bh) ^ bX[g]) << 4);
                    asm volatile("ldmatrix.sync.aligned.m8n8.x4.shared.b16 {%0,%1,%2,%3}, [%4];"
                                 : "=r"(bn[g][0]), "=r"(bn[g][1]), "=r"(bn[g][2]), "=r"(bn[g][3])
                                 : "r"(addr));
                }
#pragma unroll
                for (int f = 0; f < 2; f++)
#pragma unroll
                    for (int g = 0; g < 4; g++) {
                        mma_bf16(c[f][g * 2], am[f][0], am[f][1], am[f][2], am[f][3],
                                 bn[g][0], bn[g][1]);
                        mma_bf16(c[f][g * 2 + 1], am[f][0], am[f][1], am[f][2], am[f][3],
                                 bn[g][2], bn[g][3]);
                    }
            }
        }
#pragma unroll
        for (int f = 0; f < 2; f++) {
            int row = m0 + warpM * 32 + f * 16 + (lane >> 2);
#pragma unroll
            for (int n = 0; n < 8; n++) {
                int col = warpN * 64 + n * 8 + (lane & 3) * 2;
                *(float2*)&g_Ri[(size_t)row * 128 + col] = make_float2(c[f][n][0], c[f][n][1]);
                *(float2*)&g_Ri[(size_t)(row + 8) * 128 + col] = make_float2(c[f][n][2], c[f][n][3]);
            }
        }
    } else {
        // ---------------- GEMM2: RuT = Pt @ adjbf[:, n-tile] ----------------
        int n0 = blockIdx.x * 128;
        int lrA = tid >> 1, lcA = (tid & 1) * 4;
        const char* gAp = (const char*)(g_Pt + (size_t)lrA * NN) + lcA * 16;
        uint32_t stoA[4];
#pragma unroll
        for (int j = 0; j < 4; j++)
            stoA[j] = lrA * 128 + (((lcA + j) ^ (lrA & 7)) << 4);

        int lrB = tid >> 2, lcB = (tid & 3) * 4;
        const char* gBp = (const char*)(g_adjbf + (size_t)lrB * NN + n0) + lcB * 16;
        uint32_t stoB[4];
#pragma unroll
        for (int j = 0; j < 4; j++)
            stoB[j] = lrB * 256 + (((lcB + j) ^ (lrB & 7)) << 4);

        int aRow[2], aX[2];
#pragma unroll
        for (int f = 0; f < 2; f++) {
            aRow[f] = warpM * 32 + f * 16 + (lane & 15);
            aX[f] = aRow[f] & 7;
        }
        int ah = lane >> 4;
        int srow0 = ((lane >> 4) & 1) * 8 + (lane & 7);
        int scb = (lane >> 3) & 1;

#pragma unroll
        for (int s = 0; s < NST - 1; s++) {
            uint32_t da = sA + s * ASTG, db = sB + s * ASTG;
#pragma unroll
            for (int j = 0; j < 4; j++) {
                cpa16(da + stoA[j], gAp + (size_t)s * 128 + j * 16);
                cpa16(db + stoB[j], gBp + (size_t)s * 64 * NN * 2 + j * 16);
            }
            asm volatile("cp.async.commit_group;" ::: "memory");
        }

        for (int it = 0; it < NITER; it++) {
            if (it <= NITER - 3)      asm volatile("cp.async.wait_group 2;" ::: "memory");
            else if (it == NITER - 2) asm volatile("cp.async.wait_group 1;" ::: "memory");
            else                      asm volatile("cp.async.wait_group 0;" ::: "memory");
            __syncthreads();
            if (it + NST - 1 < NITER) {
                int s = (it + NST - 1) & (NST - 1);
                uint32_t da = sA + s * ASTG, db = sB + s * ASTG;
                size_t kit = (size_t)(it + NST - 1);
#pragma unroll
                for (int j = 0; j < 4; j++) {
                    cpa16(da + stoA[j], gAp + kit * 128 + j * 16);
                    cpa16(db + stoB[j], gBp + kit * 64 * NN * 2 + j * 16);
                }
                asm volatile("cp.async.commit_group;" ::: "memory");
            }
            uint32_t ba = sA + (it & (NST - 1)) * ASTG;
            uint32_t bb = sB + (it & (NST - 1)) * ASTG;
#pragma unroll
            for (int ks = 0; ks < 4; ks++) {
                uint32_t am[2][4], bn[4][4];
#pragma unroll
                for (int f = 0; f < 2; f++) {
                    uint32_t addr = ba + aRow[f] * 128 + ((((ks << 1) | ah) ^ aX[f]) << 4);
                    asm volatile("ldmatrix.sync.aligned.m8n8.x4.shared.b16 {%0,%1,%2,%3}, [%4];"
                                 : "=r"(am[f][0]), "=r"(am[f][1]), "=r"(am[f][2]), "=r"(am[f][3])
                                 : "r"(addr));
                }
                int srow = ks * 16 + srow0;
                int sxr = srow & 7;
#pragma unroll
                for (int g = 0; g < 4; g++) {
                    int sc = warpN * 8 + g * 2 + scb;
                    uint32_t addr = bb + srow * 256 + ((sc ^ sxr) << 4);
                    asm volatile("ldmatrix.sync.aligned.m8n8.x4.trans.shared.b16 {%0,%1,%2,%3}, [%4];"
                                 : "=r"(bn[g][0]), "=r"(bn[g][1]), "=r"(bn[g][2]), "=r"(bn[g][3])
                                 : "r"(addr));
                }
#pragma unroll
                for (int f = 0; f < 2; f++)
#pragma unroll
                    for (int g = 0; g < 4; g++) {
                        mma_bf16(c[f][g * 2], am[f][0], am[f][1], am[f][2], am[f][3],
                                 bn[g][0], bn[g][2]);
                        mma_bf16(c[f][g * 2 + 1], am[f][0], am[f][1], am[f][2], am[f][3],
                                 bn[g][1], bn[g][3]);
                    }
            }
        }

        // transpose epilogue: smem [128n][132] fp32, then coalesced rows of g_Ru
        __syncthreads();
        float* tr = (float*)sm;
#pragma unroll
        for (int f = 0; f < 2; f++) {
            int m = warpM * 32 + f * 16 + (lane >> 2);
#pragma unroll
            for (int n = 0; n < 8; n++) {
                int nc = warpN * 64 + n * 8 + (lane & 3) * 2;
                tr[nc * 132 + m] = c[f][n][0];
                tr[(nc + 1) * 132 + m] = c[f][n][1];
                tr[nc * 132 + m + 8] = c[f][n][2];
                tr[(nc + 1) * 132 + m + 8] = c[f][n][3];
            }
        }
        __syncthreads();
        for (int i = tid; i < 128 * 32; i += 256) {
            int r = i >> 5, q = i & 31;
            float4 v = *(float4*)&tr[r * 132 + q * 4];
            *(float4*)&g_Ru[(size_t)(n0 + r) * 128 + q * 4] = v;
        }
    }
}

// ---------------- 7) epilogue ----------------
__global__ void __launch_bounds__(256) final_kernel(const float* __restrict__ user,
                                                    const float* __restrict__ item,
                                                    const float* __restrict__ W2,
                                                    float* __restrict__ out) {
    int var = blockIdx.y;  // 0 -> updated_user (Ru, cinv), 1 -> updated_item (Ri, rinv)
    const float* R = var ? g_Ri : g_Ru;
    const float* scl = var ? g_rinv : g_cinv;
    const float* src = var ? user : item;
    const float* tgt = var ? item : user;
    float* o = out + (size_t)var * NN * DD;

    __shared__ __align__(16) float Ws[DD * DD];
    __shared__ float Hs[16 * DD];
    int tid = threadIdx.x;
    for (int i = tid; i < DD * DD; i += 256) Ws[i] = W2[i];

    int r0 = blockIdx.x * 16;
    int row = tid >> 4;
    int cg = (tid & 15) * 4;
    int gr = r0 + row;
    float s = scl[gr];
#pragma unroll
    for (int j = 0; j < 4; j++)
        Hs[row * DD + cg + j] = src[gr * DD + cg + j] * (s * R[gr * 128 + 64 + cg + j]);
    __syncthreads();

    float acc[4] = {0.f, 0.f, 0.f, 0.f};
#pragma unroll 8
    for (int k = 0; k < DD; k++) {
        float hh = Hs[row * DD + k];
        float4 w = *(const float4*)&Ws[k * DD + cg];
        acc[0] += hh * w.x; acc[1] += hh * w.y; acc[2] += hh * w.z; acc[3] += hh * w.w;
    }
#pragma unroll
    for (int j = 0; j < 4; j++) {
        float x = s * R[gr * 128 + cg + j] + acc[j] + tgt[gr * DD + cg + j];
        o[gr * DD + cg + j] = x > 0.f ? x : 0.2f * x;
    }
}

// ---------------- launch ----------------
extern "C" void kernel_launch(void* const* d_in, const int* in_sizes, int n_in,
                              void* d_out, int out_size) {
    const float* user = (const float*)d_in[0];
    const float* item = (const float*)d_in[1];
    const float* adj  = (const float*)d_in[2];
    const float* W1   = (const float*)d_in[3];
    const float* W2   = (const float*)d_in[4];
    float* out = (float*)d_out;

    cudaFuncSetAttribute(gemm_kernel, cudaFuncAttributeMaxDynamicSharedMemorySize,
                         2 * NST * ASTG);

    zero_kernel<<<32, 256>>>();
    convert_kernel<<<4096, 256>>>(adj);
    sums_kernel<<<128, 256>>>();
    scale_kernel<<<32, 256>>>();
    prep_kernel<<<dim3(128, 2), 256>>>(user, item, W1);
    gemm_kernel<<<dim3(64, 2), 256, 2 * NST * ASTG>>>();
    final_kernel<<<dim3(512, 2), 256>>>(user, item, W2, out);
}